// round 4
// baseline (speedup 1.0000x reference)
#include <cuda_runtime.h>
#include <cuda_bf16.h>
#include <cstdint>

#define NB    32
#define CC    256
#define HH    56
#define WWD   56
#define HWH   (HH*WWD)        /* 3136  */
#define NPIX  (NB*HWH)        /* 100352 */
#define KKT   2304            /* 256*9 */
#define EPSV  1e-5f

// ---------------- static device scratch (no allocations allowed) ----------------
__device__ uint32_t g_abits[NPIX * 8];        // packed sign bits, 8 words / pixel  (3.2 MB)
__device__ uint32_t g_wbits[CC * 72];         // packed weight bits, 72 words / oc
__device__ float    g_alpha[CC];
__device__ float    g_a[NPIX];                // channel mean per pixel
__device__ float    g_K[NPIX];                // 3x3 box of g_a / 9
__device__ float    g_s1[CC], g_h1[CC];       // bn1 scale / shift
__device__ float    g_s2[CC], g_h2[CC];       // bn2 scale / shift
__device__ float    g_r[(size_t)NPIX * CC];   // relu(conv1) fp32 (102.8 MB)

// ================= BN statistics: one block per channel, fixed-order reduce ====
__global__ void bn_stats_kernel(const float* __restrict__ x,
                                const float* __restrict__ gamma,
                                const float* __restrict__ beta,
                                float* __restrict__ scale,
                                float* __restrict__ shift)
{
    const int c = blockIdx.x;
    float s = 0.f, s2 = 0.f;
    for (int n = 0; n < NB; n++) {
        const float* p = x + ((size_t)n * CC + c) * HWH;
        for (int i = threadIdx.x; i < HWH; i += blockDim.x) {
            float v = p[i];
            s  += v;
            s2 += v * v;
        }
    }
    __shared__ float sh[512], sh2[512];
    sh[threadIdx.x]  = s;
    sh2[threadIdx.x] = s2;
    __syncthreads();
    for (int o = 256; o > 0; o >>= 1) {
        if (threadIdx.x < o) {
            sh[threadIdx.x]  += sh[threadIdx.x + o];
            sh2[threadIdx.x] += sh2[threadIdx.x + o];
        }
        __syncthreads();
    }
    if (threadIdx.x == 0) {
        const float inv_n = 1.0f / (float)((size_t)NB * HWH);
        float m   = sh[0] * inv_n;
        float var = sh2[0] * inv_n - m * m;
        float sc  = gamma[c] * rsqrtf(var + EPSV);
        scale[c] = sc;
        shift[c] = beta[c] - m * sc;
    }
}

// ================= weight prep: alpha[oc] + bit pack ===========================
__global__ void wprep_kernel(const float* __restrict__ w,
                             float* __restrict__ alpha,
                             uint32_t* __restrict__ wbits)
{
    const int oc = blockIdx.x;
    const float* wp = w + (size_t)oc * KKT;   // [ic][ky][kx]

    float s = 0.f;
    for (int i = threadIdx.x; i < KKT; i += 256) s += fabsf(wp[i]);
    __shared__ float sh[256];
    sh[threadIdx.x] = s;
    __syncthreads();
    for (int o = 128; o > 0; o >>= 1) {
        if (threadIdx.x < o) sh[threadIdx.x] += sh[threadIdx.x + o];
        __syncthreads();
    }
    if (threadIdx.x == 0) alpha[oc] = sh[0] * (1.0f / (float)KKT);

    if (threadIdx.x < 72) {
        const int t  = threadIdx.x >> 3;   // tap 0..8 (ky*3+kx)
        const int wd = threadIdx.x & 7;    // word 0..7
        uint32_t bits = 0;
        #pragma unroll
        for (int b = 0; b < 32; b++) {
            int ch = wd * 32 + b;
            float v = wp[ch * 9 + t];
            bits |= (v > 0.f ? 1u : 0u) << b;
        }
        wbits[oc * 72 + t * 8 + wd] = bits;
    }
}

// ====== BN apply + sign-pack + channel mean. 8 warps x 32 lanes; warp=32 ch ====
__global__ void bn_apply_pack_kernel(const float* __restrict__ x,
                                     const float* __restrict__ scale,
                                     const float* __restrict__ shift,
                                     uint32_t* __restrict__ abits,
                                     float* __restrict__ amean)
{
    const int lane = threadIdx.x & 31;
    const int wy   = threadIdx.x >> 5;        // 0..7 -> channels [32wy, 32wy+32)
    const int pix  = blockIdx.x * 32 + lane;  // global pixel (stays inside one n)
    const int n = pix / HWH;
    const int p = pix - n * HWH;

    const float* base = x + ((size_t)n * CC + wy * 32) * HWH + p;
    uint32_t bits = 0;
    float s = 0.f;
    #pragma unroll
    for (int i = 0; i < 32; i++) {
        const int c = wy * 32 + i;
        float v = fmaf(base[(size_t)i * HWH], scale[c], shift[c]);
        s += v;
        bits |= (v > 0.f ? 1u : 0u) << i;
    }
    abits[(size_t)pix * 8 + wy] = bits;

    __shared__ float sh[8][32];
    sh[wy][lane] = s;
    __syncthreads();
    if (wy == 0) {
        float t = 0.f;
        #pragma unroll
        for (int k = 0; k < 8; k++) t += sh[k][lane];   // fixed order
        amean[pix] = t * (1.0f / 256.0f);
    }
}

// ================= 3x3 box filter / 9 with zero padding ========================
__global__ void box3_kernel(const float* __restrict__ a, float* __restrict__ K)
{
    const int idx = blockIdx.x * 256 + threadIdx.x;
    if (idx >= NPIX) return;
    const int n = idx / HWH;
    const int p = idx - n * HWH;
    const int h = p / WWD;
    const int w = p - h * WWD;
    const float* an = a + (size_t)n * HWH;
    float s = 0.f;
    #pragma unroll
    for (int dy = -1; dy <= 1; dy++) {
        int hh = h + dy;
        if (hh < 0 || hh >= HH) continue;
        #pragma unroll
        for (int dx = -1; dx <= 1; dx++) {
            int ww = w + dx;
            if (ww < 0 || ww >= WWD) continue;
            s += an[hh * WWD + ww];
        }
    }
    K[idx] = s * (1.0f / 9.0f);
}

// ================= binary conv: XNOR-popcount, alpha*K epilogue =================
// grid: (NPIX/32, 4) ; block 256 = 8 warps. Warp = 32 pixels; warp wy handles
// oc in [ocbase+8wy, ocbase+8wy+8). Weights for 64 oc staged in smem, broadcast
// LDS.128 reads (all lanes same address -> conflict-free).
template <bool FUSE_RES>
__global__ void __launch_bounds__(256)
binconv_kernel(const uint32_t* __restrict__ abits,
               const uint32_t* __restrict__ wbits,
               const float*    __restrict__ alpha,
               const float*    __restrict__ Ksc,
               const float*    __restrict__ res,
               float*          __restrict__ out)
{
    __shared__ __align__(16) uint32_t ws[64 * 72];   // 18 KB
    __shared__ float sal[64];

    const int ocbase = blockIdx.y * 64;
    for (int i = threadIdx.x; i < 64 * 72; i += 256) ws[i] = wbits[ocbase * 72 + i];
    if (threadIdx.x < 64) sal[threadIdx.x] = alpha[ocbase + threadIdx.x];
    __syncthreads();

    const int lane = threadIdx.x & 31;
    const int wy   = threadIdx.x >> 5;
    const int pix  = blockIdx.x * 32 + lane;
    const int n = pix / HWH;
    const int p = pix - n * HWH;
    const int h = p / WWD;
    const int w = p - h * WWD;
    const float kv = Ksc[pix];

    int acc[8];
    #pragma unroll
    for (int i = 0; i < 8; i++) acc[i] = 0;
    int nvalid = 0;

    const uint32_t* wsp = ws + (wy * 8) * 72;

    #pragma unroll
    for (int dy = -1; dy <= 1; dy++) {
        const int hh = h + dy;
        const bool vy = (hh >= 0) && (hh < HH);
        #pragma unroll
        for (int dx = -1; dx <= 1; dx++) {
            const int ww = w + dx;
            if (vy && ww >= 0 && ww < WWD) {
                nvalid++;
                const uint32_t* ap = abits + ((size_t)(n * HWH + hh * WWD + ww)) * 8;
                const uint4 a0 = *reinterpret_cast<const uint4*>(ap);
                const uint4 a1 = *reinterpret_cast<const uint4*>(ap + 4);
                const int t = (dy + 1) * 3 + (dx + 1);
                #pragma unroll
                for (int i = 0; i < 8; i++) {
                    const uint4 w0 = *reinterpret_cast<const uint4*>(wsp + i * 72 + t * 8);
                    const uint4 w1 = *reinterpret_cast<const uint4*>(wsp + i * 72 + t * 8 + 4);
                    int p0 = __popc(a0.x ^ w0.x), p1 = __popc(a0.y ^ w0.y);
                    int p2 = __popc(a0.z ^ w0.z), p3 = __popc(a0.w ^ w0.w);
                    int p4 = __popc(a1.x ^ w1.x), p5 = __popc(a1.y ^ w1.y);
                    int p6 = __popc(a1.z ^ w1.z), p7 = __popc(a1.w ^ w1.w);
                    acc[i] += ((p0 + p1) + (p2 + p3)) + ((p4 + p5) + (p6 + p7));
                }
            }
        }
    }

    #pragma unroll
    for (int i = 0; i < 8; i++) {
        const int oc = ocbase + wy * 8 + i;
        const float dot = (float)(256 * nvalid - 2 * acc[i]);
        float v = sal[wy * 8 + i] * kv * dot;
        if (FUSE_RES) v += res[((size_t)n * CC + oc) * HWH + p];
        out[((size_t)n * CC + oc) * HWH + p] = fmaxf(v, 0.f);
    }
}

// ================================ launcher =====================================
extern "C" void kernel_launch(void* const* d_in, const int* in_sizes, int n_in,
                              void* d_out, int out_size)
{
    (void)in_sizes; (void)n_in; (void)out_size;
    const float* x  = (const float*)d_in[0];
    const float* g1 = (const float*)d_in[1];
    const float* b1 = (const float*)d_in[2];
    const float* w1 = (const float*)d_in[3];
    const float* g2 = (const float*)d_in[4];
    const float* b2 = (const float*)d_in[5];
    const float* w2 = (const float*)d_in[6];
    float* out = (float*)d_out;

    uint32_t *abits, *wbits;
    float *alpha, *a, *K, *s1, *h1, *s2, *h2, *r;
    cudaGetSymbolAddress((void**)&abits, g_abits);
    cudaGetSymbolAddress((void**)&wbits, g_wbits);
    cudaGetSymbolAddress((void**)&alpha, g_alpha);
    cudaGetSymbolAddress((void**)&a,     g_a);
    cudaGetSymbolAddress((void**)&K,     g_K);
    cudaGetSymbolAddress((void**)&s1,    g_s1);
    cudaGetSymbolAddress((void**)&h1,    g_h1);
    cudaGetSymbolAddress((void**)&s2,    g_s2);
    cudaGetSymbolAddress((void**)&h2,    g_h2);
    cudaGetSymbolAddress((void**)&r,     g_r);

    const dim3 cgrid(NPIX / 32, 4);

    // ---- stage 1: BN1 -> pack -> K1 -> binary conv1 (+ReLU) ----
    bn_stats_kernel<<<CC, 512>>>(x, g1, b1, s1, h1);
    wprep_kernel<<<CC, 256>>>(w1, alpha, wbits);
    bn_apply_pack_kernel<<<NPIX / 32, 256>>>(x, s1, h1, abits, a);
    box3_kernel<<<NPIX / 256, 256>>>(a, K);
    binconv_kernel<false><<<cgrid, 256>>>(abits, wbits, alpha, K, nullptr, r);

    // ---- stage 2: BN2 -> pack -> K2 -> binary conv2 + identity + ReLU ----
    bn_stats_kernel<<<CC, 512>>>(r, g2, b2, s2, h2);
    wprep_kernel<<<CC, 256>>>(w2, alpha, wbits);
    bn_apply_pack_kernel<<<NPIX / 32, 256>>>(r, s2, h2, abits, a);
    box3_kernel<<<NPIX / 256, 256>>>(a, K);
    binconv_kernel<true><<<cgrid, 256>>>(abits, wbits, alpha, K, x, out);
}